// round 7
// baseline (speedup 1.0000x reference)
#include <cuda_runtime.h>

// Reference semantics reduce to (softmax over a size-1 axis == 1; W is dead code):
//   out[i, 0:512]    = 2*X[i]                              for i < 64
//   out[i, 0:512]    = X[i] + sum_{r=i-64..i-1} X[r]       for i >= 64
//   out[i, 512:1024] = X[i]
//
// Prefix decomposition with chunk = LENS = 64:
//   PL[i] = intra-chunk inclusive row prefix,  T[k] = chunk-k total
//   W[i]  = PL[i-1] - PL[i-65] + T[(i-65)>>6]   (i >= 65),  W[64] = PL[63]
//
// This round: occupancy-first shaping. Small per-thread state, launch_bounds
// targeting 8 blocks/SM, all loads independent.

#define NROWS 4096
#define DCOLS 512
#define LENS  64
#define D4    (DCOLS / 4)     // 128 float4 per input row
#define OD4   (2 * D4)        // 256 float4 per output row
#define NCH   (NROWS / LENS)  // 64 chunks
#define SEG   8               // rows per scan segment
#define NSEG  (LENS / SEG)    // 8 segments per chunk
#define CPG   16              // f4 columns per scan block (128 threads = 8 seg x 16 col)
#define NCG   (D4 / CPG)      // 8 column groups
#define K2R   2               // rows per K2 block

__device__ float4 g_PL[NROWS * D4];   // 8 MB
__device__ float4 g_T[NCH * D4];      // 32 KB

static __device__ __forceinline__ float4 f4add(float4 a, float4 b) {
    return make_float4(a.x + b.x, a.y + b.y, a.z + b.z, a.w + b.w);
}
static __device__ __forceinline__ float4 f4sub(float4 a, float4 b) {
    return make_float4(a.x - b.x, a.y - b.y, a.z - b.z, a.w - b.w);
}

// K1: blocks 0..511  -> segmented prefix scan (chunk k = b>>3, col group g = b&7)
//     blocks 512..543 -> rows 0..63 copy (2 rows each)
__global__ __launch_bounds__(128, 8) void prefix_kernel(
    const float4* __restrict__ X4, float4* __restrict__ O4)
{
    const int b = blockIdx.x;

    if (b >= NCH * NCG) {
        const int i0 = (b - NCH * NCG) * 2;
        const int c  = threadIdx.x;          // f4 column 0..127
        #pragma unroll
        for (int r = 0; r < 2; ++r) {
            const int i = i0 + r;
            float4 x = X4[(size_t)i * D4 + c];
            O4[(size_t)i * OD4 + c]      = f4add(x, x);
            O4[(size_t)i * OD4 + D4 + c] = x;
        }
        return;
    }

    const int k    = b >> 3;                 // chunk
    const int g    = b & 7;                  // column group
    const int lane = threadIdx.x & (CPG - 1);
    const int s    = threadIdx.x / CPG;      // segment 0..7
    const int c    = g * CPG + lane;

    const int row0 = k * LENS + s * SEG;
    const float4* px = X4 + (size_t)row0 * D4 + c;

    float4 v[SEG];
    #pragma unroll
    for (int r = 0; r < SEG; ++r) v[r] = px[(size_t)r * D4];
    #pragma unroll
    for (int r = 1; r < SEG; ++r) v[r] = f4add(v[r], v[r - 1]);

    __shared__ float4 stot[NSEG][CPG];
    stot[s][lane] = v[SEG - 1];
    __syncthreads();

    float4 off = make_float4(0.f, 0.f, 0.f, 0.f);
    #pragma unroll
    for (int j = 0; j < NSEG - 1; ++j)
        if (s > j) off = f4add(off, stot[j][lane]);

    float4* ppl = g_PL + (size_t)row0 * D4 + c;
    #pragma unroll
    for (int r = 0; r < SEG; ++r) ppl[(size_t)r * D4] = f4add(v[r], off);

    if (s == NSEG - 1)
        g_T[(size_t)k * D4 + c] = f4add(v[SEG - 1], off);
}

// K2: block b -> output rows 64+2b, 64+2b+1. Fully parallel, 8 loads in flight.
__global__ __launch_bounds__(128, 8) void window_out_kernel(
    const float4* __restrict__ X4, float4* __restrict__ O4)
{
    const int c  = threadIdx.x;
    const int i0 = LENS + K2R * blockIdx.x;
    const float4 zero = make_float4(0.f, 0.f, 0.f, 0.f);

    float4 x[K2R], pl1[K2R], pl2[K2R], tt[K2R];
    #pragma unroll
    for (int r = 0; r < K2R; ++r) {
        const int i    = i0 + r;
        const int idx2 = i - 65;
        x[r]   = X4[(size_t)i * D4 + c];
        pl1[r] = g_PL[(size_t)(i - 1) * D4 + c];
        if (idx2 >= 0) {
            pl2[r] = g_PL[(size_t)idx2 * D4 + c];
            tt[r]  = g_T[(size_t)(idx2 >> 6) * D4 + c];
        } else {                     // only i == 64
            pl2[r] = zero;
            tt[r]  = zero;
        }
    }

    #pragma unroll
    for (int r = 0; r < K2R; ++r) {
        const int i = i0 + r;
        float4 w = f4add(f4sub(pl1[r], pl2[r]), tt[r]);
        O4[(size_t)i * OD4 + c]      = f4add(x[r], w);
        O4[(size_t)i * OD4 + D4 + c] = x[r];
    }
}

extern "C" void kernel_launch(void* const* d_in, const int* in_sizes, int n_in,
                              void* d_out, int out_size)
{
    const float4* X4 = (const float4*)d_in[0];   // X: (4096, 512) f32
    float4* O4 = (float4*)d_out;                 // out: (4096, 1024) f32

    prefix_kernel<<<NCH * NCG + LENS / 2, 128>>>(X4, O4);        // 544 blocks
    window_out_kernel<<<(NROWS - LENS) / K2R, 128>>>(X4, O4);    // 2016 blocks
}

// round 8
// speedup vs baseline: 1.2657x; 1.2657x over previous
#include <cuda_runtime.h>

// Reference semantics reduce to (softmax over a size-1 axis == 1; W is dead code):
//   out[i, 0:512]    = 2*X[i]                              for i < 64
//   out[i, 0:512]    = X[i] + sum_{r=i-64..i-1} X[r]       for i >= 64
//   out[i, 512:1024] = X[i]
//
// SINGLE fused kernel (no scratch, no graph dependency edges):
// block = (chunk k of 64 output rows, group g of 8 float4 columns).
// For k>=1: load the 128 rows [64(k-1), 64k+64), build an exclusive prefix
// P[0..128] in smem (P[m] = sum of first m loaded rows), then
//   W[64k+t] = P[t+64] - P[t],  out_left = x + W, out_right = x.
// For k==0: plain 2X | X copy.

#define NROWS 4096
#define DCOLS 512
#define LENS  64
#define D4    (DCOLS / 4)   // 128 f4 per input row
#define OD4   (2 * D4)      // 256 f4 per output row
#define CPB   8             // f4 columns per block
#define NG    (D4 / CPB)    // 16 column groups
#define NCH   (NROWS / LENS) // 64 chunks
#define SEG   8             // rows per load segment
#define NSEG  16            // 128 rows / 8

static __device__ __forceinline__ float4 f4add(float4 a, float4 b) {
    return make_float4(a.x + b.x, a.y + b.y, a.z + b.z, a.w + b.w);
}
static __device__ __forceinline__ float4 f4sub(float4 a, float4 b) {
    return make_float4(a.x - b.x, a.y - b.y, a.z - b.z, a.w - b.w);
}

__global__ __launch_bounds__(128, 8) void fused_window_kernel(
    const float4* __restrict__ X4, float4* __restrict__ O4)
{
    const int b = blockIdx.x;
    const int k = b >> 4;            // chunk 0..63
    const int g = b & 15;            // column group 0..15
    const int tid = threadIdx.x;
    const int c   = tid & 7;         // column within group
    const int col = g * CPB + c;     // global f4 column

    if (k == 0) {
        // rows 0..63: left = 2X, right = X. 16 row-teams x 4 rows.
        const int u = tid >> 3;
        #pragma unroll
        for (int r = 0; r < 4; ++r) {
            const int i = u * 4 + r;
            float4 x = X4[(size_t)i * D4 + col];
            O4[(size_t)i * OD4 + col]      = f4add(x, x);
            O4[(size_t)i * OD4 + D4 + col] = x;
        }
        return;
    }

    __shared__ float4 P[129 * CPB];      // exclusive prefix over 128 loaded rows
    __shared__ float4 tot[NSEG * CPB];   // per-segment totals

    // ---- Load + local inclusive prefix (8 independent LDG.128, chain of 8) ----
    const int s    = tid >> 3;           // segment 0..15
    const int base = (k - 1) * LENS;     // first loaded global row
    const float4* px = X4 + (size_t)(base + s * SEG) * D4 + col;

    float4 v[SEG];
    #pragma unroll
    for (int j = 0; j < SEG; ++j) v[j] = px[(size_t)j * D4];
    #pragma unroll
    for (int j = 1; j < SEG; ++j) v[j] = f4add(v[j], v[j - 1]);

    tot[s * CPB + c] = v[SEG - 1];
    __syncthreads();

    float4 off = make_float4(0.f, 0.f, 0.f, 0.f);
    for (int j = 0; j < s; ++j) off = f4add(off, tot[j * CPB + c]);

    // Exclusive prefix: P[m] = sum of loaded rows [0, m)
    if (s == 0) P[c] = off;              // off == 0 here -> P[0] = 0
    #pragma unroll
    for (int j = 0; j < SEG; ++j)
        P[(s * SEG + j + 1) * CPB + c] = f4add(v[j], off);
    __syncthreads();

    // ---- Emit 64 output rows: W[t] = P[t+64] - P[t] ----
    const int u = tid >> 3;              // row team 0..15
    #pragma unroll
    for (int r = 0; r < 4; ++r) {
        const int t = u * 4 + r;         // 0..63
        const int i = k * LENS + t;      // global output row
        float4 w  = f4sub(P[(t + 64) * CPB + c], P[t * CPB + c]);
        float4 x  = X4[(size_t)i * D4 + col];
        O4[(size_t)i * OD4 + col]      = f4add(x, w);
        O4[(size_t)i * OD4 + D4 + col] = x;
    }
}

extern "C" void kernel_launch(void* const* d_in, const int* in_sizes, int n_in,
                              void* d_out, int out_size)
{
    const float4* X4 = (const float4*)d_in[0];   // X: (4096, 512) f32
    float4* O4 = (float4*)d_out;                 // out: (4096, 1024) f32

    fused_window_kernel<<<NCH * NG, 128>>>(X4, O4);   // 1024 blocks, 1 launch
}